// round 1
// baseline (speedup 1.0000x reference)
#include <cuda_runtime.h>
#include <cuda_bf16.h>
#include <stdint.h>

// Problem shape (LlamaMorExpertRouter_30477087933212)
#define B 4
#define S 4096
#define H 2048
#define K 2048
#define ALPHA 0.1f

// Output layout in d_out (float32): out[B*K*H] | sel[B*K] | targets[B*S]
#define OUT_OFF   ((size_t)0)
#define SEL_OFF   ((size_t)B * K * H)
#define TGT_OFF   (SEL_OFF + (size_t)B * K)

// Scratch (no device allocs allowed in kernel_launch)
__device__ float g_probs[B * S];
__device__ int   g_sel[B * K];

// ---------------------------------------------------------------------------
// Kernel 1: router projection + sigmoid*alpha. One warp per token.
// Reads x (128 MiB) + w (L1-resident). HBM-bound.
// ---------------------------------------------------------------------------
__global__ __launch_bounds__(256) void router_kernel(
    const float* __restrict__ x, const float* __restrict__ w)
{
    int warp = (blockIdx.x * blockDim.x + threadIdx.x) >> 5;
    int lane = threadIdx.x & 31;
    if (warp >= B * S) return;

    const float4* xr = reinterpret_cast<const float4*>(x + (size_t)warp * H);
    const float4* wr = reinterpret_cast<const float4*>(w);

    float acc = 0.0f;
#pragma unroll
    for (int i = 0; i < H / (4 * 32); i++) {   // 16 iters
        float4 a = xr[lane + 32 * i];
        float4 b = wr[lane + 32 * i];
        acc += a.x * b.x + a.y * b.y + a.z * b.z + a.w * b.w;
    }
#pragma unroll
    for (int o = 16; o; o >>= 1)
        acc += __shfl_xor_sync(0xFFFFFFFFu, acc, o);

    if (lane == 0) {
        // sigmoid(acc) * alpha  (full-precision expf to track reference)
        float p = ALPHA / (1.0f + expf(-acc));
        g_probs[warp] = p;
    }
}

// ---------------------------------------------------------------------------
// Kernel 2: per-batch top-K selection via shared-memory bitonic sort of
// 64-bit keys (prob_bits<<32 | (S-1-i)); probs are strictly positive so
// float-bit ordering == value ordering. Descending sort; ties prefer smaller
// original index (matching jax.lax.top_k). Then flags + block prefix-sum to
// emit indices in ascending order; also writes sel (as float) and targets.
// One block (1024 threads) per batch. Tiny, off the roofline path.
// ---------------------------------------------------------------------------
__global__ __launch_bounds__(1024) void select_kernel(
    float* __restrict__ out_sel, float* __restrict__ out_tgt)
{
    __shared__ unsigned long long keys[S];      // 32 KB
    __shared__ unsigned char flag[S];           // 4 KB
    __shared__ int partial[1024];               // 4 KB

    const int b = blockIdx.x;
    const int t = threadIdx.x;
    const float* p = g_probs + b * S;

    for (int i = t; i < S; i += 1024) {
        unsigned bits = __float_as_uint(p[i]);  // positive floats
        keys[i] = ((unsigned long long)bits << 32) | (unsigned)(S - 1 - i);
    }
    __syncthreads();

    // bitonic sort, descending
    for (int k = 2; k <= S; k <<= 1) {
        for (int j = k >> 1; j > 0; j >>= 1) {
            for (int i = t; i < S; i += 1024) {
                int ixj = i ^ j;
                if (ixj > i) {
                    unsigned long long a = keys[i], c = keys[ixj];
                    bool up = ((i & k) == 0);
                    // descending overall: swap if out of order
                    if (up ? (a < c) : (a > c)) {
                        keys[i] = c;
                        keys[ixj] = a;
                    }
                }
            }
            __syncthreads();
        }
    }

    for (int i = t; i < S; i += 1024) flag[i] = 0;
    __syncthreads();
    for (int i = t; i < K; i += 1024) {
        int idx = S - 1 - (int)(keys[i] & 0xFFFFFFFFu);
        flag[idx] = 1;
    }
    __syncthreads();

    // each thread owns 4 consecutive token indices
    int base = t * 4;
    int s0 = flag[base + 0], s1 = flag[base + 1];
    int s2 = flag[base + 2], s3 = flag[base + 3];
    int mysum = s0 + s1 + s2 + s3;
    partial[t] = mysum;
    __syncthreads();

    // Hillis-Steele inclusive scan over 1024 partials
    for (int off = 1; off < 1024; off <<= 1) {
        int v = (t >= off) ? partial[t - off] : 0;
        __syncthreads();
        partial[t] += v;
        __syncthreads();
    }
    int r = partial[t] - mysum;   // exclusive prefix

    int*   selp = g_sel + b * K;
    float* selo = out_sel + (size_t)b * K;
    float* tgto = out_tgt + (size_t)b * S;

#pragma unroll
    for (int q = 0; q < 4; q++) {
        int idx = base + q;
        int f = flag[idx];
        tgto[idx] = f ? 1.0f : 0.0f;
        if (f) {
            selp[r] = idx;
            selo[r] = (float)idx;
            r++;
        }
    }
}

// ---------------------------------------------------------------------------
// Kernel 3: gather selected tokens and scale by router prob.
// One block (256 thr) per (b, rank). 64 MiB read + 64 MiB write. HBM-bound.
// ---------------------------------------------------------------------------
__global__ __launch_bounds__(256) void gather_kernel(
    const float* __restrict__ x, float* __restrict__ out)
{
    int bj = blockIdx.x;                 // 0 .. B*K-1
    int b  = bj / K;
    int idx = g_sel[bj];
    float wv = g_probs[b * S + idx];

    const float4* src = reinterpret_cast<const float4*>(
        x + ((size_t)b * S + (size_t)idx) * H);
    float4* dst = reinterpret_cast<float4*>(out + (size_t)bj * H);

#pragma unroll
    for (int k = 0; k < 2; k++) {        // H/4 = 512 = 2 * 256
        int i = threadIdx.x + k * 256;
        float4 v = src[i];
        v.x *= wv; v.y *= wv; v.z *= wv; v.w *= wv;
        dst[i] = v;
    }
}

// ---------------------------------------------------------------------------
extern "C" void kernel_launch(void* const* d_in, const int* in_sizes, int n_in,
                              void* d_out, int out_size)
{
    const float* x = (const float*)d_in[0];        // [B,S,H] f32
    const float* w = (const float*)d_in[1];        // [1,H]   f32
    float* out = (float*)d_out;

    float* out_main = out + OUT_OFF;   // [B,K,H]
    float* out_sel  = out + SEL_OFF;   // [B,K]
    float* out_tgt  = out + TGT_OFF;   // [B,S]

    // 1) router probs: one warp/token, 8 tokens/block
    router_kernel<<<(B * S) / 8, 256>>>(x, w);

    // 2) per-batch top-K selection + sel/targets outputs
    select_kernel<<<B, 1024>>>(out_sel, out_tgt);

    // 3) gather + scale
    gather_kernel<<<B * K, 256>>>(x, out_main);
}

// round 2
// speedup vs baseline: 1.1692x; 1.1692x over previous
#include <cuda_runtime.h>
#include <cuda_bf16.h>
#include <stdint.h>

// Problem shape (LlamaMorExpertRouter_30477087933212)
#define B 4
#define S 4096
#define H 2048
#define K 2048
#define ALPHA 0.1f

// Output layout in d_out (float32): out[B*K*H] | sel[B*K] | targets[B*S]
#define SEL_OFF   ((size_t)B * K * H)
#define TGT_OFF   (SEL_OFF + (size_t)B * K)

// Scratch (no device allocs allowed)
__device__ float g_probs[B * S];
__device__ int   g_sel[B * K];

// ---------------------------------------------------------------------------
// Kernel 1: router projection + sigmoid*alpha. One warp per token.
// Reads x (128 MiB) + w (cache-resident). HBM-bound.
// ---------------------------------------------------------------------------
__global__ __launch_bounds__(256) void router_kernel(
    const float* __restrict__ x, const float* __restrict__ w)
{
    int warp = (blockIdx.x * blockDim.x + threadIdx.x) >> 5;
    int lane = threadIdx.x & 31;
    if (warp >= B * S) return;

    const float4* xr = reinterpret_cast<const float4*>(x + (size_t)warp * H);
    const float4* wr = reinterpret_cast<const float4*>(w);

    float acc0 = 0.0f, acc1 = 0.0f;
#pragma unroll
    for (int i = 0; i < H / (4 * 64); i++) {   // 8 iters, 2 loads each
        float4 a0 = xr[lane + 64 * i];
        float4 b0 = wr[lane + 64 * i];
        float4 a1 = xr[lane + 32 + 64 * i];
        float4 b1 = wr[lane + 32 + 64 * i];
        acc0 += a0.x * b0.x + a0.y * b0.y + a0.z * b0.z + a0.w * b0.w;
        acc1 += a1.x * b1.x + a1.y * b1.y + a1.z * b1.z + a1.w * b1.w;
    }
    float acc = acc0 + acc1;
#pragma unroll
    for (int o = 16; o; o >>= 1)
        acc += __shfl_xor_sync(0xFFFFFFFFu, acc, o);

    if (lane == 0) {
        float p = ALPHA / (1.0f + expf(-acc));   // sigmoid * alpha
        g_probs[warp] = p;
    }
}

// ---------------------------------------------------------------------------
// Block-wide exclusive scan (1024 threads) via warp shuffles. 2 barriers.
// ---------------------------------------------------------------------------
__device__ __forceinline__ int block_exscan(int v)
{
    __shared__ int wsum[32];
    int lane = threadIdx.x & 31;
    int wid  = threadIdx.x >> 5;

    __syncthreads();                 // protect wsum reuse across calls
    int inc = v;
#pragma unroll
    for (int o = 1; o < 32; o <<= 1) {
        int y = __shfl_up_sync(0xFFFFFFFFu, inc, o);
        if (lane >= o) inc += y;
    }
    if (lane == 31) wsum[wid] = inc;
    __syncthreads();
    if (wid == 0) {
        int s = wsum[lane];
#pragma unroll
        for (int o = 1; o < 32; o <<= 1) {
            int y = __shfl_up_sync(0xFFFFFFFFu, s, o);
            if (lane >= o) s += y;
        }
        wsum[lane] = s;
    }
    __syncthreads();
    int warp_excl = (wid == 0) ? 0 : wsum[wid - 1];
    return warp_excl + inc - v;
}

// ---------------------------------------------------------------------------
// Kernel 2: per-batch top-K via MSB radix select on float bits (positive
// probs => bit order == value order). 4 passes of 8-bit histograms with
// warp-aggregated atomics. Ties at the threshold value are broken toward
// SMALLER index (matching jax.lax.top_k). Emits sel (ascending, as float),
// targets, and g_sel for the gather. One 1024-thread block per batch.
// ---------------------------------------------------------------------------
__global__ __launch_bounds__(1024) void select_kernel(
    float* __restrict__ out_sel, float* __restrict__ out_tgt)
{
    __shared__ unsigned sbits[S];      // 16 KB
    __shared__ int hist[256];
    __shared__ int sh_d, sh_cum;

    const int b = blockIdx.x;
    const int t = threadIdx.x;
    const int lane = t & 31;

    for (int i = t; i < S; i += 1024)
        sbits[i] = __float_as_uint(g_probs[b * S + i]);
    __syncthreads();

    unsigned prefix = 0, prefmask = 0;
    int remaining = K;

#pragma unroll
    for (int pass = 0; pass < 4; pass++) {
        int shift = 24 - 8 * pass;
        if (t < 256) hist[t] = 0;
        __syncthreads();

        for (int i = t; i < S; i += 1024) {
            unsigned v = sbits[i];
            bool ok = ((v & prefmask) == prefix);
            unsigned key = ok ? ((v >> shift) & 255u) : 0x100u;
            unsigned peers = __match_any_sync(0xFFFFFFFFu, key);
            if (ok) {
                int leader = __ffs(peers) - 1;
                if (lane == leader)
                    atomicAdd(&hist[key], __popc(peers));
            }
        }
        __syncthreads();

        if (t == 0) {
            int cum = 0, d = 255;
            for (; d > 0; d--) {
                if (cum + hist[d] >= remaining) break;
                cum += hist[d];
            }
            sh_d = d; sh_cum = cum;
        }
        __syncthreads();
        remaining -= sh_cum;
        prefix |= ((unsigned)sh_d) << shift;
        prefmask |= 0xFFu << shift;
        __syncthreads();
    }

    const unsigned T = prefix;   // exact bits of K-th largest value
    const int R = remaining;     // how many ties (bits==T) to take, by smallest index

    // Each thread owns 4 consecutive token indices.
    const int base = t * 4;
    unsigned v0 = sbits[base + 0], v1 = sbits[base + 1];
    unsigned v2 = sbits[base + 2], v3 = sbits[base + 3];

    int e0 = (v0 == T), e1 = (v1 == T), e2 = (v2 == T), e3 = (v3 == T);
    int eqpre = block_exscan(e0 + e1 + e2 + e3);

    int s0 = (v0 > T) || (e0 && (eqpre            < R));
    int s1 = (v1 > T) || (e1 && (eqpre + e0       < R));
    int s2 = (v2 > T) || (e2 && (eqpre + e0 + e1  < R));
    int s3 = (v3 > T) || (e3 && (eqpre + e0 + e1 + e2 < R));

    int pos = block_exscan(s0 + s1 + s2 + s3);

    int*   selp = g_sel   + b * K;
    float* selo = out_sel + (size_t)b * K;
    float* tgto = out_tgt + (size_t)b * S;

    int sv[4] = {s0, s1, s2, s3};
#pragma unroll
    for (int q = 0; q < 4; q++) {
        int idx = base + q;
        tgto[idx] = sv[q] ? 1.0f : 0.0f;
        if (sv[q]) {
            selp[pos] = idx;
            selo[pos] = (float)idx;
            pos++;
        }
    }
}

// ---------------------------------------------------------------------------
// Kernel 3: gather selected tokens and scale by router prob. HBM-bound.
// ---------------------------------------------------------------------------
__global__ __launch_bounds__(256) void gather_kernel(
    const float* __restrict__ x, float* __restrict__ out)
{
    int bj = blockIdx.x;                 // 0 .. B*K-1
    int b  = bj / K;
    int idx = g_sel[bj];
    float wv = g_probs[b * S + idx];

    const float4* src = reinterpret_cast<const float4*>(
        x + ((size_t)b * S + (size_t)idx) * H);
    float4* dst = reinterpret_cast<float4*>(out + (size_t)bj * H);

#pragma unroll
    for (int k = 0; k < 2; k++) {        // H/4 = 512 = 2 * 256
        int i = threadIdx.x + k * 256;
        float4 v = src[i];
        v.x *= wv; v.y *= wv; v.z *= wv; v.w *= wv;
        dst[i] = v;
    }
}

// ---------------------------------------------------------------------------
extern "C" void kernel_launch(void* const* d_in, const int* in_sizes, int n_in,
                              void* d_out, int out_size)
{
    const float* x = (const float*)d_in[0];        // [B,S,H] f32
    const float* w = (const float*)d_in[1];        // [1,H]   f32
    float* out = (float*)d_out;

    float* out_main = out;             // [B,K,H]
    float* out_sel  = out + SEL_OFF;   // [B,K]
    float* out_tgt  = out + TGT_OFF;   // [B,S]

    router_kernel<<<(B * S) / 8, 256>>>(x, w);
    select_kernel<<<B, 1024>>>(out_sel, out_tgt);
    gather_kernel<<<B * K, 256>>>(x, out_main);
}

// round 3
// speedup vs baseline: 1.6132x; 1.3798x over previous
#include <cuda_runtime.h>
#include <cuda_bf16.h>
#include <stdint.h>

// Problem shape (LlamaMorExpertRouter_30477087933212)
#define B 4
#define S 4096
#define H 2048
#define K 2048
#define ALPHA 0.1f

// Output layout in d_out (float32): out[B*K*H] | sel[B*K] | targets[B*S]
#define SEL_OFF   ((size_t)B * K * H)
#define TGT_OFF   (SEL_OFF + (size_t)B * K)

// Scratch (no device allocs allowed)
__device__ float g_probs[B * S];
__device__ int   g_sel[B * K];

// ---------------------------------------------------------------------------
// Kernel 1: router projection + sigmoid*alpha. One warp per token. HBM-bound.
// ---------------------------------------------------------------------------
__global__ __launch_bounds__(256) void router_kernel(
    const float* __restrict__ x, const float* __restrict__ w)
{
    int warp = (blockIdx.x * blockDim.x + threadIdx.x) >> 5;
    int lane = threadIdx.x & 31;
    if (warp >= B * S) return;

    const float4* xr = reinterpret_cast<const float4*>(x + (size_t)warp * H);
    const float4* wr = reinterpret_cast<const float4*>(w);

    float acc0 = 0.0f, acc1 = 0.0f;
#pragma unroll
    for (int i = 0; i < H / (4 * 64); i++) {   // 8 iters, 2 loads each
        float4 a0 = xr[lane + 64 * i];
        float4 b0 = wr[lane + 64 * i];
        float4 a1 = xr[lane + 32 + 64 * i];
        float4 b1 = wr[lane + 32 + 64 * i];
        acc0 += a0.x * b0.x + a0.y * b0.y + a0.z * b0.z + a0.w * b0.w;
        acc1 += a1.x * b1.x + a1.y * b1.y + a1.z * b1.z + a1.w * b1.w;
    }
    float acc = acc0 + acc1;
#pragma unroll
    for (int o = 16; o; o >>= 1)
        acc += __shfl_xor_sync(0xFFFFFFFFu, acc, o);

    if (lane == 0)
        g_probs[warp] = ALPHA / (1.0f + expf(-acc));   // sigmoid * alpha
}

// ---------------------------------------------------------------------------
// Block-wide exclusive scan (1024 threads) via warp shuffles.
// ---------------------------------------------------------------------------
__device__ __forceinline__ int block_exscan(int v, int* wsum)
{
    int lane = threadIdx.x & 31;
    int wid  = threadIdx.x >> 5;

    __syncthreads();                 // protect wsum reuse across calls
    int inc = v;
#pragma unroll
    for (int o = 1; o < 32; o <<= 1) {
        int y = __shfl_up_sync(0xFFFFFFFFu, inc, o);
        if (lane >= o) inc += y;
    }
    if (lane == 31) wsum[wid] = inc;
    __syncthreads();
    if (wid == 0) {
        int s = wsum[lane];
#pragma unroll
        for (int o = 1; o < 32; o <<= 1) {
            int y = __shfl_up_sync(0xFFFFFFFFu, s, o);
            if (lane >= o) s += y;
        }
        wsum[lane] = s;
    }
    __syncthreads();
    int warp_excl = (wid == 0) ? 0 : wsum[wid - 1];
    return warp_excl + inc - v;
}

// ---------------------------------------------------------------------------
// Kernel 2: per-batch top-K via MSB radix select on float bits (positive
// probs => bit order == value order). Values live in registers (one float4
// per thread). Histogram via warp-aggregated atomics; threshold bucket found
// with a PARALLEL 256-thread suffix scan (no serial walk). Ties at the
// threshold break toward smaller index (matching jax.lax.top_k).
// One 1024-thread block per batch.
// ---------------------------------------------------------------------------
__global__ __launch_bounds__(1024) void select_kernel(
    float* __restrict__ out_sel, float* __restrict__ out_tgt)
{
    __shared__ int hist[256];
    __shared__ int wsum[32];
    __shared__ int sh_d, sh_cum;

    const int b = blockIdx.x;
    const int t = threadIdx.x;
    const int lane = t & 31;
    const int base = t * 4;

    // one coalesced float4 per thread: 4 consecutive token probs
    float4 pv = reinterpret_cast<const float4*>(g_probs + b * S)[t];
    unsigned v0 = __float_as_uint(pv.x), v1 = __float_as_uint(pv.y);
    unsigned v2 = __float_as_uint(pv.z), v3 = __float_as_uint(pv.w);

    unsigned prefix = 0, prefmask = 0;
    int remaining = K;

#pragma unroll
    for (int pass = 0; pass < 4; pass++) {
        const int shift = 24 - 8 * pass;
        if (t < 256) hist[t] = 0;
        __syncthreads();

        // histogram from registers, warp-aggregated atomics
        unsigned vals[4] = {v0, v1, v2, v3};
#pragma unroll
        for (int q = 0; q < 4; q++) {
            unsigned v = vals[q];
            bool ok = ((v & prefmask) == prefix);
            unsigned key = ok ? ((v >> shift) & 255u) : 0x100u;
            unsigned peers = __match_any_sync(0xFFFFFFFFu, key);
            if (ok && lane == (__ffs(peers) - 1))
                atomicAdd(&hist[key], __popc(peers));
        }
        __syncthreads();

        // parallel suffix scan over 256 buckets: thread t owns bucket 255-t
        int hv = 0, incw = 0;
        if (t < 256) {
            hv = hist[255 - t];
            incw = hv;
#pragma unroll
            for (int o = 1; o < 32; o <<= 1) {
                int y = __shfl_up_sync(0xFFFFFFFFu, incw, o);
                if (lane >= o) incw += y;
            }
            if (lane == 31) wsum[t >> 5] = incw;
        }
        __syncthreads();
        if (t < 256) {
            int add = 0;
            int wid8 = t >> 5;
#pragma unroll
            for (int j = 0; j < 8; j++)
                if (j < wid8) add += wsum[j];
            int incl = incw + add;      // suffix sum down to this bucket
            int excl = incl - hv;       // sum of strictly higher buckets
            if (excl < remaining && remaining <= incl) {
                sh_d = 255 - t;
                sh_cum = excl;
            }
        }
        __syncthreads();
        remaining -= sh_cum;
        prefix |= ((unsigned)sh_d) << shift;
        prefmask |= 0xFFu << shift;
        __syncthreads();
    }

    const unsigned T = prefix;   // exact bits of K-th largest value
    const int R = remaining;     // ties (bits==T) to take, by smallest index

    int e0 = (v0 == T), e1 = (v1 == T), e2 = (v2 == T), e3 = (v3 == T);
    int eqpre = block_exscan(e0 + e1 + e2 + e3, wsum);

    int s0 = (v0 > T) || (e0 && (eqpre                 < R));
    int s1 = (v1 > T) || (e1 && (eqpre + e0            < R));
    int s2 = (v2 > T) || (e2 && (eqpre + e0 + e1       < R));
    int s3 = (v3 > T) || (e3 && (eqpre + e0 + e1 + e2  < R));

    int pos = block_exscan(s0 + s1 + s2 + s3, wsum);

    int*   selp = g_sel   + b * K;
    float* selo = out_sel + (size_t)b * K;
    float* tgto = out_tgt + (size_t)b * S;

    int sv[4] = {s0, s1, s2, s3};
#pragma unroll
    for (int q = 0; q < 4; q++) {
        int idx = base + q;
        tgto[idx] = sv[q] ? 1.0f : 0.0f;
        if (sv[q]) {
            selp[pos] = idx;
            selo[pos] = (float)idx;
            pos++;
        }
    }
}

// ---------------------------------------------------------------------------
// Kernel 3: gather selected tokens and scale. Streaming stores (__stcs) keep
// the output from evicting x (still partly L2-resident after the router).
// ---------------------------------------------------------------------------
__global__ __launch_bounds__(256) void gather_kernel(
    const float* __restrict__ x, float* __restrict__ out)
{
    int bj = blockIdx.x;                 // 0 .. B*K-1
    int b  = bj / K;
    int idx = g_sel[bj];
    float wv = g_probs[b * S + idx];

    const float4* src = reinterpret_cast<const float4*>(
        x + ((size_t)b * S + (size_t)idx) * H);
    float4* dst = reinterpret_cast<float4*>(out + (size_t)bj * H);

#pragma unroll
    for (int k = 0; k < 2; k++) {        // H/4 = 512 = 2 * 256
        int i = threadIdx.x + k * 256;
        float4 v = src[i];
        v.x *= wv; v.y *= wv; v.z *= wv; v.w *= wv;
        __stcs(&dst[i], v);
    }
}

// ---------------------------------------------------------------------------
extern "C" void kernel_launch(void* const* d_in, const int* in_sizes, int n_in,
                              void* d_out, int out_size)
{
    const float* x = (const float*)d_in[0];        // [B,S,H] f32
    const float* w = (const float*)d_in[1];        // [1,H]   f32
    float* out = (float*)d_out;

    float* out_main = out;             // [B,K,H]
    float* out_sel  = out + SEL_OFF;   // [B,K]
    float* out_tgt  = out + TGT_OFF;   // [B,S]

    router_kernel<<<(B * S) / 8, 256>>>(x, w);
    select_kernel<<<B, 1024>>>(out_sel, out_tgt);
    gather_kernel<<<B * K, 256>>>(x, out_main);
}